// round 2
// baseline (speedup 1.0000x reference)
#include <cuda_runtime.h>

// Collapsed affine map: out = x @ M + c, M is [16][4], c is [4].
__device__ float g_M[16 * 4];
__device__ float g_c[4];

// ---------------------------------------------------------------------------
// Kernel A: fold the 62-layer linear chain into (M, c).
// 128 threads: tid -> (r = tid/8 in [0,16), c = tid%8 in [0,8)).
// M state is [16][8] in smem (x -> hidden map so far); v is the bias state [8].
// ---------------------------------------------------------------------------
__global__ void build_composite(const float* __restrict__ W1,
                                const float* __restrict__ b1,
                                const float* __restrict__ Ws,
                                const float* __restrict__ bs,
                                const float* __restrict__ W2,
                                const float* __restrict__ b2) {
    __shared__ float M[2][16 * 8];
    __shared__ float v[2][8];

    const int tid = threadIdx.x;           // 0..127
    const int r = tid >> 3;                // input-channel index 0..15
    const int c = tid & 7;                 // hidden index 0..7

    // Init: M = W1^T  (W1 is [8,16] row-major); v = b1.
    M[0][r * 8 + c] = W1[c * 16 + r];
    if (tid < 8) v[0][tid] = b1[tid];
    __syncthreads();

    int cur = 0;
    for (int k = 0; k < 60; ++k) {
        const float* W = Ws + k * 64;      // [8,8] row-major: W[cc*8 + j]
        float acc = 0.0f;
#pragma unroll
        for (int j = 0; j < 8; ++j)
            acc += M[cur][r * 8 + j] * W[c * 8 + j];
        M[cur ^ 1][r * 8 + c] = acc;

        if (tid < 8) {
            float a = bs[k * 8 + tid];
#pragma unroll
            for (int j = 0; j < 8; ++j)
                a += v[cur][j] * W[tid * 8 + j];
            v[cur ^ 1][tid] = a;
        }
        __syncthreads();
        cur ^= 1;
    }

    // Final projection with W2 [4,8]: M_final [16][4], c_final [4].
    if (c < 4) {
        float acc = 0.0f;
#pragma unroll
        for (int j = 0; j < 8; ++j)
            acc += M[cur][r * 8 + j] * W2[c * 8 + j];
        g_M[r * 4 + c] = acc;
    }
    if (tid < 4) {
        float a = b2[tid];
#pragma unroll
        for (int j = 0; j < 8; ++j)
            a += v[cur][j] * W2[tid * 8 + j];
        g_c[tid] = a;
    }
}

// ---------------------------------------------------------------------------
// Kernel B: streaming GEMV. One thread per row: 4x float4 load, 1x float4 store.
// HBM-bound: 80 B/row traffic, 64 FMA/row.
// ---------------------------------------------------------------------------
__global__ __launch_bounds__(256) void apply_affine(
    const float4* __restrict__ x4, float4* __restrict__ y4, int n_rows) {
    __shared__ float sM[64];
    __shared__ float sc[4];
    const int tid = threadIdx.x;
    if (tid < 64) sM[tid] = g_M[tid];
    if (tid < 4) sc[tid] = g_c[tid];
    __syncthreads();

    const int row = blockIdx.x * blockDim.x + tid;
    if (row >= n_rows) return;

    const float4 a = x4[row * 4 + 0];
    const float4 b = x4[row * 4 + 1];
    const float4 cdat = x4[row * 4 + 2];
    const float4 d = x4[row * 4 + 3];

    const float xr[16] = {a.x, a.y, a.z, a.w,
                          b.x, b.y, b.z, b.w,
                          cdat.x, cdat.y, cdat.z, cdat.w,
                          d.x, d.y, d.z, d.w};

    float o0 = sc[0], o1 = sc[1], o2 = sc[2], o3 = sc[3];
#pragma unroll
    for (int i = 0; i < 16; ++i) {
        const float xi = xr[i];
        o0 += xi * sM[i * 4 + 0];
        o1 += xi * sM[i * 4 + 1];
        o2 += xi * sM[i * 4 + 2];
        o3 += xi * sM[i * 4 + 3];
    }
    y4[row] = make_float4(o0, o1, o2, o3);
}

// ---------------------------------------------------------------------------
// Launch: inputs in metadata order: x, W1, b1, Ws, bs, W2, b2.
// ---------------------------------------------------------------------------
extern "C" void kernel_launch(void* const* d_in, const int* in_sizes, int n_in,
                              void* d_out, int out_size) {
    const float* x  = (const float*)d_in[0];   // [B,16]
    const float* W1 = (const float*)d_in[1];   // [8,16]
    const float* b1 = (const float*)d_in[2];   // [8]
    const float* Ws = (const float*)d_in[3];   // [60,8,8]
    const float* bs = (const float*)d_in[4];   // [60,8]
    const float* W2 = (const float*)d_in[5];   // [4,8]
    const float* b2 = (const float*)d_in[6];   // [4]
    float* out = (float*)d_out;                // [B,4]

    const int n_rows = in_sizes[0] / 16;       // 4194304

    build_composite<<<1, 128>>>(W1, b1, Ws, bs, W2, b2);

    const int threads = 256;
    const int blocks = (n_rows + threads - 1) / threads;
    apply_affine<<<blocks, threads>>>((const float4*)x, (float4*)out, n_rows);
}

// round 4
// speedup vs baseline: 1.6333x; 1.6333x over previous
#include <cuda_runtime.h>

// Collapsed affine map: out = x @ M + c, M is [16][4], c is [4].
__device__ float g_M[16 * 4];
__device__ float g_c[4];

// ---------------------------------------------------------------------------
// Kernel A: fold the 62-layer linear chain into (M, c).
// v2: stage ALL weights/biases into smem with coalesced float4 loads first,
// so the 60-step dependency chain never touches DRAM.
// ---------------------------------------------------------------------------
__global__ void build_composite(const float* __restrict__ W1,
                                const float* __restrict__ b1,
                                const float* __restrict__ Ws,
                                const float* __restrict__ bs,
                                const float* __restrict__ W2,
                                const float* __restrict__ b2) {
    __shared__ float sW[60 * 64];   // 15360 B
    __shared__ float sb[60 * 8];    //  1920 B
    __shared__ float M[2][16 * 8];
    __shared__ float v[2][8];

    const int tid = threadIdx.x;    // 0..127

    // Coalesced staging: 960 float4 of Ws, 120 float4 of bs.
    {
        const float4* W4 = (const float4*)Ws;
        float4* sW4 = (float4*)sW;
#pragma unroll
        for (int i = 0; i < 8; ++i)          // 8 * 128 = 1024 >= 960
            if (tid + i * 128 < 960) sW4[tid + i * 128] = W4[tid + i * 128];
        const float4* b4 = (const float4*)bs;
        float4* sb4 = (float4*)sb;
        if (tid < 120) sb4[tid] = b4[tid];
    }

    const int r = tid >> 3;                 // input-channel 0..15
    const int c = tid & 7;                  // hidden 0..7

    // Init: M = W1^T (W1 is [8,16] row-major); v = b1.
    M[0][r * 8 + c] = W1[c * 16 + r];
    if (tid < 8) v[0][tid] = b1[tid];
    __syncthreads();

    int cur = 0;
    for (int k = 0; k < 60; ++k) {
        const float* W = sW + k * 64;       // [8,8] row-major in smem
        float acc = 0.0f;
#pragma unroll
        for (int j = 0; j < 8; ++j)
            acc += M[cur][r * 8 + j] * W[c * 8 + j];
        M[cur ^ 1][r * 8 + c] = acc;

        if (tid < 8) {
            float a = sb[k * 8 + tid];
#pragma unroll
            for (int j = 0; j < 8; ++j)
                a += v[cur][j] * W[tid * 8 + j];
            v[cur ^ 1][tid] = a;
        }
        __syncthreads();
        cur ^= 1;
    }

    // Final projection with W2 [4,8]: M_final [16][4], c_final [4].
    if (c < 4) {
        float acc = 0.0f;
#pragma unroll
        for (int j = 0; j < 8; ++j)
            acc += M[cur][r * 8 + j] * W2[c * 8 + j];
        g_M[r * 4 + c] = acc;
    }
    if (tid < 4) {
        float a = b2[tid];
#pragma unroll
        for (int j = 0; j < 8; ++j)
            a += v[cur][j] * W2[tid * 8 + j];
        g_c[tid] = a;
    }
}

// ---------------------------------------------------------------------------
// Kernel B: streaming GEMV, 2 rows per thread for 8 outstanding LDG.128.
// Streaming cache hints: zero reuse, evict-first.
// ---------------------------------------------------------------------------
__global__ __launch_bounds__(256) void apply_affine(
    const float4* __restrict__ x4, float4* __restrict__ y4, int n_rows) {
    __shared__ float sM[64];
    __shared__ float sc[4];
    const int tid = threadIdx.x;
    if (tid < 64) sM[tid] = g_M[tid];
    if (tid < 4) sc[tid] = g_c[tid];
    __syncthreads();

    const int r0 = blockIdx.x * (blockDim.x * 2) + tid;
    const int r1 = r0 + blockDim.x;

    // Issue all 8 loads up front (deep MLP).
    float4 xa[2][4];
    const bool ok0 = (r0 < n_rows);
    const bool ok1 = (r1 < n_rows);
    if (ok0) {
#pragma unroll
        for (int i = 0; i < 4; ++i) xa[0][i] = __ldcs(&x4[(size_t)r0 * 4 + i]);
    }
    if (ok1) {
#pragma unroll
        for (int i = 0; i < 4; ++i) xa[1][i] = __ldcs(&x4[(size_t)r1 * 4 + i]);
    }

#pragma unroll
    for (int s = 0; s < 2; ++s) {
        const int row = s ? r1 : r0;
        if (row >= n_rows) continue;

        const float xr[16] = {
            xa[s][0].x, xa[s][0].y, xa[s][0].z, xa[s][0].w,
            xa[s][1].x, xa[s][1].y, xa[s][1].z, xa[s][1].w,
            xa[s][2].x, xa[s][2].y, xa[s][2].z, xa[s][2].w,
            xa[s][3].x, xa[s][3].y, xa[s][3].z, xa[s][3].w};

        float o0 = sc[0], o1 = sc[1], o2 = sc[2], o3 = sc[3];
#pragma unroll
        for (int i = 0; i < 16; ++i) {
            const float xi = xr[i];
            o0 += xi * sM[i * 4 + 0];
            o1 += xi * sM[i * 4 + 1];
            o2 += xi * sM[i * 4 + 2];
            o3 += xi * sM[i * 4 + 3];
        }
        __stcs(&y4[row], make_float4(o0, o1, o2, o3));
    }
}

// ---------------------------------------------------------------------------
// Launch: inputs in metadata order: x, W1, b1, Ws, bs, W2, b2.
// ---------------------------------------------------------------------------
extern "C" void kernel_launch(void* const* d_in, const int* in_sizes, int n_in,
                              void* d_out, int out_size) {
    const float* x  = (const float*)d_in[0];   // [B,16]
    const float* W1 = (const float*)d_in[1];   // [8,16]
    const float* b1 = (const float*)d_in[2];   // [8]
    const float* Ws = (const float*)d_in[3];   // [60,8,8]
    const float* bs = (const float*)d_in[4];   // [60,8]
    const float* W2 = (const float*)d_in[5];   // [4,8]
    const float* b2 = (const float*)d_in[6];   // [4]
    float* out = (float*)d_out;                // [B,4]

    const int n_rows = in_sizes[0] / 16;       // 4194304

    build_composite<<<1, 128>>>(W1, b1, Ws, bs, W2, b2);

    const int threads = 256;
    const int rows_per_block = threads * 2;
    const int blocks = (n_rows + rows_per_block - 1) / rows_per_block;
    apply_affine<<<blocks, threads>>>((const float4*)x, (float4*)out, n_rows);
}

// round 5
// speedup vs baseline: 1.7582x; 1.0765x over previous
#include <cuda_runtime.h>

#define NMID 60

// Collapsed affine map: out = x @ M + c, M is [16][4], c is [4].
__device__ float g_M[16 * 4];
__device__ float g_c[4];

// ---------------------------------------------------------------------------
// Kernel A (v3): fold the 62-layer linear chain into (M, c) via an associative
// TREE reduction over affine maps (W,b): depth 6 instead of 60 serial steps.
// 512 threads. All operands staged in smem first (coalesced float4).
// ---------------------------------------------------------------------------
__global__ __launch_bounds__(512) void build_composite(
    const float* __restrict__ W1, const float* __restrict__ b1,
    const float* __restrict__ Ws, const float* __restrict__ bs,
    const float* __restrict__ W2, const float* __restrict__ b2) {
    // Ping-pong affine buffers: W acts as h_new = W h + b (row-major [8][8]).
    __shared__ float Wb[2][NMID * 64];   // 2 * 15360 B
    __shared__ float bb[2][NMID * 8];    // 2 * 1920 B
    __shared__ float A1[8 * 16];         // chain ∘ W1
    __shared__ float v1[8];

    const int tid = threadIdx.x;  // 0..511

    // Stage Ws (960 float4) and bs (120 float4) coalesced.
    {
        const float4* W4 = (const float4*)Ws;
        float4* dW = (float4*)&Wb[0][0];
        for (int i = tid; i < NMID * 16; i += 512) dW[i] = W4[i];
        const float4* b4 = (const float4*)bs;
        float4* db = (float4*)&bb[0][0];
        if (tid < NMID * 2) db[tid] = b4[tid];
    }
    __syncthreads();

    // Tree reduction: counts 60 -> 30 -> 15 -> 8 -> 4 -> 2 -> 1.
    int cur = 0, cnt = NMID;
    while (cnt > 1) {
        const int half = cnt >> 1;
        const int nxt = cur ^ 1;

        // W products: out[p] = A_{2p+1} * A_{2p}   (later * earlier)
        for (int idx = tid; idx < half * 64; idx += 512) {
            const int p = idx >> 6, e = idx & 63, i = e >> 3, j = e & 7;
            const float* A = &Wb[cur][(2 * p + 1) * 64];
            const float* B = &Wb[cur][(2 * p) * 64];
            float acc = 0.0f;
#pragma unroll
            for (int k = 0; k < 8; ++k) acc += A[i * 8 + k] * B[k * 8 + j];
            Wb[nxt][p * 64 + e] = acc;
        }
        // Bias: b_out = A_{2p+1} * b_{2p} + b_{2p+1}
        for (int idx = tid; idx < half * 8; idx += 512) {
            const int p = idx >> 3, i = idx & 7;
            const float* A = &Wb[cur][(2 * p + 1) * 64];
            const float* bB = &bb[cur][(2 * p) * 8];
            const float* bA = &bb[cur][(2 * p + 1) * 8];
            float acc = bA[i];
#pragma unroll
            for (int k = 0; k < 8; ++k) acc += A[i * 8 + k] * bB[k];
            bb[nxt][p * 8 + i] = acc;
        }
        // Odd element passes through unchanged.
        if (cnt & 1) {
            for (int idx = tid; idx < 64; idx += 512)
                Wb[nxt][half * 64 + idx] = Wb[cur][(cnt - 1) * 64 + idx];
            if (tid < 8) bb[nxt][half * 8 + tid] = bb[cur][(cnt - 1) * 8 + tid];
        }
        __syncthreads();
        cnt = half + (cnt & 1);
        cur = nxt;
    }

    // Fold in W1/b1: A1[k][i] = sum_j T[k][j] * W1[j][i]; v1 = T*b1 + bchain.
    const float* T = &Wb[cur][0];
    const float* bchain = &bb[cur][0];
    for (int idx = tid; idx < 128; idx += 512) {
        const int k = idx >> 4, i = idx & 15;
        float acc = 0.0f;
#pragma unroll
        for (int j = 0; j < 8; ++j) acc += T[k * 8 + j] * W1[j * 16 + i];
        A1[k * 16 + i] = acc;
    }
    if (tid < 8) {
        float acc = bchain[tid];
#pragma unroll
        for (int j = 0; j < 8; ++j) acc += T[tid * 8 + j] * b1[j];
        v1[tid] = acc;
    }
    __syncthreads();

    // Fold in W2/b2: g_M[i][o] = sum_k W2[o][k] * A1[k][i]; g_c = W2*v1 + b2.
    if (tid < 64) {
        const int i = tid >> 2, o = tid & 3;
        float acc = 0.0f;
#pragma unroll
        for (int k = 0; k < 8; ++k) acc += W2[o * 8 + k] * A1[k * 16 + i];
        g_M[tid] = acc;
    }
    if (tid < 4) {
        float acc = b2[tid];
#pragma unroll
        for (int k = 0; k < 8; ++k) acc += W2[tid * 8 + k] * v1[k];
        g_c[tid] = acc;
    }
}

// ---------------------------------------------------------------------------
// Kernel B: streaming GEMV, 4 rows per thread (16 front-batched LDG.128).
// ---------------------------------------------------------------------------
__global__ __launch_bounds__(256) void apply_affine(
    const float4* __restrict__ x4, float4* __restrict__ y4, int n_rows) {
    __shared__ float sM[64];
    __shared__ float sc[4];
    const int tid = threadIdx.x;
    if (tid < 64) sM[tid] = g_M[tid];
    if (tid < 4) sc[tid] = g_c[tid];
    __syncthreads();

    const int base = blockIdx.x * (blockDim.x * 4) + tid;

    // Front-batch all loads for maximum MLP.
    float4 xa[4][4];
#pragma unroll
    for (int s = 0; s < 4; ++s) {
        const int row = base + s * 256;
        if (row < n_rows) {
#pragma unroll
            for (int i = 0; i < 4; ++i)
                xa[s][i] = __ldcs(&x4[(size_t)row * 4 + i]);
        }
    }

#pragma unroll
    for (int s = 0; s < 4; ++s) {
        const int row = base + s * 256;
        if (row >= n_rows) continue;

        const float xr[16] = {
            xa[s][0].x, xa[s][0].y, xa[s][0].z, xa[s][0].w,
            xa[s][1].x, xa[s][1].y, xa[s][1].z, xa[s][1].w,
            xa[s][2].x, xa[s][2].y, xa[s][2].z, xa[s][2].w,
            xa[s][3].x, xa[s][3].y, xa[s][3].z, xa[s][3].w};

        float o0 = sc[0], o1 = sc[1], o2 = sc[2], o3 = sc[3];
#pragma unroll
        for (int i = 0; i < 16; ++i) {
            const float xi = xr[i];
            o0 += xi * sM[i * 4 + 0];
            o1 += xi * sM[i * 4 + 1];
            o2 += xi * sM[i * 4 + 2];
            o3 += xi * sM[i * 4 + 3];
        }
        __stcs(&y4[row], make_float4(o0, o1, o2, o3));
    }
}

// ---------------------------------------------------------------------------
// Launch: inputs in metadata order: x, W1, b1, Ws, bs, W2, b2.
// ---------------------------------------------------------------------------
extern "C" void kernel_launch(void* const* d_in, const int* in_sizes, int n_in,
                              void* d_out, int out_size) {
    const float* x  = (const float*)d_in[0];   // [B,16]
    const float* W1 = (const float*)d_in[1];   // [8,16]
    const float* b1 = (const float*)d_in[2];   // [8]
    const float* Ws = (const float*)d_in[3];   // [60,8,8]
    const float* bs = (const float*)d_in[4];   // [60,8]
    const float* W2 = (const float*)d_in[5];   // [4,8]
    const float* b2 = (const float*)d_in[6];   // [4]
    float* out = (float*)d_out;                // [B,4]

    const int n_rows = in_sizes[0] / 16;       // 4194304

    build_composite<<<1, 512>>>(W1, b1, Ws, bs, W2, b2);

    const int threads = 256;
    const int rows_per_block = threads * 4;
    const int blocks = (n_rows + rows_per_block - 1) / rows_per_block;
    apply_affine<<<blocks, threads>>>((const float4*)x, (float4*)out, n_rows);
}

// round 6
// speedup vs baseline: 1.8261x; 1.0386x over previous
#include <cuda_runtime.h>

#define NMID 60

// Collapsed affine map: out = x @ M + c, M is [16][4], c is [4].
__device__ float g_M[16 * 4];
__device__ float g_c[4];

// ---------------------------------------------------------------------------
// Kernel A: fold the 62-layer linear chain into (M, c) via an associative
// TREE reduction over affine maps (W,b): depth 6. Triggers PDL completion
// as soon as g_M/g_c are globally visible.
// ---------------------------------------------------------------------------
__global__ __launch_bounds__(512) void build_composite(
    const float* __restrict__ W1, const float* __restrict__ b1,
    const float* __restrict__ Ws, const float* __restrict__ bs,
    const float* __restrict__ W2, const float* __restrict__ b2) {
    __shared__ float Wb[2][NMID * 64];
    __shared__ float bb[2][NMID * 8];
    __shared__ float A1[8 * 16];
    __shared__ float v1[8];

    const int tid = threadIdx.x;  // 0..511

    // Stage Ws (960 float4) and bs (120 float4) coalesced.
    {
        const float4* W4 = (const float4*)Ws;
        float4* dW = (float4*)&Wb[0][0];
        for (int i = tid; i < NMID * 16; i += 512) dW[i] = W4[i];
        const float4* b4 = (const float4*)bs;
        float4* db = (float4*)&bb[0][0];
        if (tid < NMID * 2) db[tid] = b4[tid];
    }
    __syncthreads();

    // Tree reduction: 60 -> 30 -> 15 -> 8 -> 4 -> 2 -> 1.
    int cur = 0, cnt = NMID;
    while (cnt > 1) {
        const int half = cnt >> 1;
        const int nxt = cur ^ 1;

        for (int idx = tid; idx < half * 64; idx += 512) {
            const int p = idx >> 6, e = idx & 63, i = e >> 3, j = e & 7;
            const float* A = &Wb[cur][(2 * p + 1) * 64];
            const float* B = &Wb[cur][(2 * p) * 64];
            float acc = 0.0f;
#pragma unroll
            for (int k = 0; k < 8; ++k) acc += A[i * 8 + k] * B[k * 8 + j];
            Wb[nxt][p * 64 + e] = acc;
        }
        for (int idx = tid; idx < half * 8; idx += 512) {
            const int p = idx >> 3, i = idx & 7;
            const float* A = &Wb[cur][(2 * p + 1) * 64];
            const float* bB = &bb[cur][(2 * p) * 8];
            const float* bA = &bb[cur][(2 * p + 1) * 8];
            float acc = bA[i];
#pragma unroll
            for (int k = 0; k < 8; ++k) acc += A[i * 8 + k] * bB[k];
            bb[nxt][p * 8 + i] = acc;
        }
        if (cnt & 1) {
            for (int idx = tid; idx < 64; idx += 512)
                Wb[nxt][half * 64 + idx] = Wb[cur][(cnt - 1) * 64 + idx];
            if (tid < 8) bb[nxt][half * 8 + tid] = bb[cur][(cnt - 1) * 8 + tid];
        }
        __syncthreads();
        cnt = half + (cnt & 1);
        cur = nxt;
    }

    // Fold in W1/b1.
    const float* T = &Wb[cur][0];
    const float* bchain = &bb[cur][0];
    for (int idx = tid; idx < 128; idx += 512) {
        const int k = idx >> 4, i = idx & 15;
        float acc = 0.0f;
#pragma unroll
        for (int j = 0; j < 8; ++j) acc += T[k * 8 + j] * W1[j * 16 + i];
        A1[k * 16 + i] = acc;
    }
    if (tid < 8) {
        float acc = bchain[tid];
#pragma unroll
        for (int j = 0; j < 8; ++j) acc += T[tid * 8 + j] * b1[j];
        v1[tid] = acc;
    }
    __syncthreads();

    // Fold in W2/b2 -> g_M, g_c.
    if (tid < 64) {
        const int i = tid >> 2, o = tid & 3;
        float acc = 0.0f;
#pragma unroll
        for (int k = 0; k < 8; ++k) acc += W2[o * 8 + k] * A1[k * 16 + i];
        g_M[tid] = acc;
    }
    if (tid < 4) {
        float acc = b2[tid];
#pragma unroll
        for (int k = 0; k < 8; ++k) acc += W2[tid * 8 + k] * v1[k];
        g_c[tid] = acc;
    }

    // Make results globally visible, then release the dependent grid.
    __threadfence();
    __syncthreads();
    cudaTriggerProgrammaticLaunchCompletion();
}

// ---------------------------------------------------------------------------
// Kernel B: streaming GEMV, 2 rows/thread (best measured config).
// PDL: issue the 8 independent x loads BEFORE gridsync so the first wave's
// DRAM traffic overlaps build_composite execution.
// ---------------------------------------------------------------------------
__global__ __launch_bounds__(256) void apply_affine(
    const float4* __restrict__ x4, float4* __restrict__ y4, int n_rows) {
    __shared__ float sM[64];
    __shared__ float sc[4];
    const int tid = threadIdx.x;

    const int r0 = blockIdx.x * (blockDim.x * 2) + tid;
    const int r1 = r0 + blockDim.x;

    // Front-batch loads (independent of build output).
    float4 xa[2][4];
    if (r0 < n_rows) {
#pragma unroll
        for (int i = 0; i < 4; ++i) xa[0][i] = __ldcs(&x4[(size_t)r0 * 4 + i]);
    }
    if (r1 < n_rows) {
#pragma unroll
        for (int i = 0; i < 4; ++i) xa[1][i] = __ldcs(&x4[(size_t)r1 * 4 + i]);
    }

    // Wait for build_composite's g_M/g_c.
    cudaGridDependencySynchronize();

    if (tid < 64) sM[tid] = g_M[tid];
    if (tid < 4) sc[tid] = g_c[tid];
    __syncthreads();

#pragma unroll
    for (int s = 0; s < 2; ++s) {
        const int row = s ? r1 : r0;
        if (row >= n_rows) continue;

        const float xr[16] = {
            xa[s][0].x, xa[s][0].y, xa[s][0].z, xa[s][0].w,
            xa[s][1].x, xa[s][1].y, xa[s][1].z, xa[s][1].w,
            xa[s][2].x, xa[s][2].y, xa[s][2].z, xa[s][2].w,
            xa[s][3].x, xa[s][3].y, xa[s][3].z, xa[s][3].w};

        float o0 = sc[0], o1 = sc[1], o2 = sc[2], o3 = sc[3];
#pragma unroll
        for (int i = 0; i < 16; ++i) {
            const float xi = xr[i];
            o0 += xi * sM[i * 4 + 0];
            o1 += xi * sM[i * 4 + 1];
            o2 += xi * sM[i * 4 + 2];
            o3 += xi * sM[i * 4 + 3];
        }
        __stcs(&y4[row], make_float4(o0, o1, o2, o3));
    }
}

// ---------------------------------------------------------------------------
// Launch: build, then apply with Programmatic Dependent Launch overlap.
// ---------------------------------------------------------------------------
extern "C" void kernel_launch(void* const* d_in, const int* in_sizes, int n_in,
                              void* d_out, int out_size) {
    const float* x  = (const float*)d_in[0];   // [B,16]
    const float* W1 = (const float*)d_in[1];   // [8,16]
    const float* b1 = (const float*)d_in[2];   // [8]
    const float* Ws = (const float*)d_in[3];   // [60,8,8]
    const float* bs = (const float*)d_in[4];   // [60,8]
    const float* W2 = (const float*)d_in[5];   // [4,8]
    const float* b2 = (const float*)d_in[6];   // [4]
    float* out = (float*)d_out;                // [B,4]

    const int n_rows = in_sizes[0] / 16;       // 4194304

    build_composite<<<1, 512>>>(W1, b1, Ws, bs, W2, b2);

    const int threads = 256;
    const int rows_per_block = threads * 2;
    const int blocks = (n_rows + rows_per_block - 1) / rows_per_block;

    cudaLaunchConfig_t cfg = {};
    cfg.gridDim = dim3(blocks);
    cfg.blockDim = dim3(threads);
    cfg.dynamicSmemBytes = 0;
    cfg.stream = 0;
    cudaLaunchAttribute attrs[1];
    attrs[0].id = cudaLaunchAttributeProgrammaticStreamSerialization;
    attrs[0].val.programmaticStreamSerializationAllowed = 1;
    cfg.attrs = attrs;
    cfg.numAttrs = 1;

    cudaError_t err = cudaLaunchKernelEx(&cfg, apply_affine,
                                         (const float4*)x, (float4*)out, n_rows);
    if (err != cudaSuccess) {
        // Fallback: plain serialized launch (still correct).
        apply_affine<<<blocks, threads>>>((const float4*)x, (float4*)out, n_rows);
    }
}